// round 16
// baseline (speedup 1.0000x reference)
#include <cuda_runtime.h>
#include <cuda_bf16.h>
#include <math.h>
#include <cstdint>

#define V_SZ 2048
#define L_SZ 16
#define H_SZ 8
#define D_SZ 64
#define B_SZ 8192
#define NW_TOTAL 8192
#define N_NAMES 2048
#define TEMP_INV 0.125f
#define SROW 20

// -------- scratch --------
__device__ float g_cq[V_SZ * H_SZ * D_SZ];
__device__ float g_ck[V_SZ * H_SZ * D_SZ];
__device__ float g_cv[V_SZ * H_SZ * D_SZ];
__device__ __nv_bfloat16 g_cqb[V_SZ * 512];
__device__ __nv_bfloat16 g_ckb[V_SZ * 512];
__device__ float g_pq[L_SZ * H_SZ * D_SZ];
__device__ float g_pk[L_SZ * H_SZ * D_SZ];
__device__ float g_pv[L_SZ * H_SZ * D_SZ];
__device__ __nv_bfloat16 g_qkh[H_SZ * V_SZ * V_SZ];   // 67MB [h][x][y]
__device__ __nv_bfloat16 g_qkb[V_SZ * V_SZ * H_SZ];   // 67MB [x][y][h]
__device__ __nv_bfloat16 g_cpb[V_SZ * L_SZ * H_SZ];   // [v][j][h]
__device__ __nv_bfloat16 g_posb[L_SZ * L_SZ * H_SZ];  // [i][j][h]
__device__ float g_pooled[B_SZ * H_SZ * D_SZ];
__device__ float g_xflat[B_SZ * 512];
__device__ int   g_segoff[N_NAMES];

// -------- K1: prep = pos-embed QKV (blocks 0..15) + char QKV (blocks 16..271) --------
__global__ __launch_bounds__(256) void prep_kernel(
    const float* __restrict__ Wp, const float* __restrict__ bp,
    const float* __restrict__ emb, const float* __restrict__ Wc, const float* __restrict__ bc) {
    int tid = threadIdx.x;
    if (blockIdx.x < 16) {
        int l = blockIdx.x;
        __shared__ float sp[64];
        if (tid < 64) {
            int f = tid & 31;
            double inv = pow(10000.0, -(double)f / 32.0);
            double ph = (double)l * inv;
            sp[tid] = (float)((tid < 32) ? cos(ph) : sin(ph));
        }
        __syncthreads();
        for (int c = tid; c < 1536; c += 256) {
            float a = 0.f;
            #pragma unroll 8
            for (int k = 0; k < 64; k++) a += sp[k] * Wp[k * 1536 + c];
            a += bp[c];
            int t = c >> 9, rem = c & 511;
            float* dst = (t == 0) ? g_pq : (t == 1) ? g_pk : g_pv;
            dst[l * 512 + rem] = a;
        }
        return;
    }
    int row0 = (blockIdx.x - 16) * 8;
    __shared__ float se[8][64];
    for (int idx = tid; idx < 512; idx += 256)
        se[idx >> 6][idx & 63] = emb[(row0 + (idx >> 6)) * 64 + (idx & 63)];
    __syncthreads();
    float acc[6][8];
    #pragma unroll
    for (int c = 0; c < 6; c++)
        #pragma unroll
        for (int r = 0; r < 8; r++) acc[c][r] = 0.f;
    for (int k = 0; k < 64; k++) {
        float w[6];
        #pragma unroll
        for (int c = 0; c < 6; c++) w[c] = Wc[k * 1536 + tid + c * 256];
        #pragma unroll
        for (int r = 0; r < 8; r++) {
            float e = se[r][k];
            #pragma unroll
            for (int c = 0; c < 6; c++) acc[c][r] = fmaf(e, w[c], acc[c][r]);
        }
    }
    #pragma unroll
    for (int c = 0; c < 6; c++) {
        int col = tid + c * 256;
        float bias = bc[col];
        int t = col >> 9, rem = col & 511;
        float* dst = (t == 0) ? g_cq : (t == 1) ? g_ck : g_cv;
        __nv_bfloat16* bdst = (t == 0) ? g_cqb : (t == 1) ? g_ckb : (__nv_bfloat16*)0;
        #pragma unroll
        for (int r = 0; r < 8; r++) {
            float val = acc[c][r] + bias;
            int idx = (row0 + r) * 512 + rem;
            dst[idx] = val;
            if (bdst) bdst[idx] = __float2bfloat16(val);
        }
    }
}

// -------- K2: char_qk GEMM via mma.sync bf16 -> bf16 [h][x][y] --------
__global__ __launch_bounds__(256) void charqk_mma_kernel() {
    __shared__ __align__(16) char smem_raw[36864];
    __nv_bfloat16* sA = (__nv_bfloat16*)smem_raw;            // [128][72]
    __nv_bfloat16* sB = sA + 128 * 72;                        // [128][72]

    int t = threadIdx.x;
    int lane = t & 31;
    int w = t >> 5;
    int X0 = blockIdx.x * 128, Y0 = blockIdx.y * 128, h = blockIdx.z;

    {
        int row = t >> 1, half = t & 1;
        const uint4* srcA = (const uint4*)&g_cqb[(size_t)(X0 + row) * 512 + h * 64 + half * 32];
        const uint4* srcB = (const uint4*)&g_ckb[(size_t)(Y0 + row) * 512 + h * 64 + half * 32];
        uint4* dstA = (uint4*)&sA[row * 72 + half * 32];
        uint4* dstB = (uint4*)&sB[row * 72 + half * 32];
        #pragma unroll
        for (int k = 0; k < 4; k++) { dstA[k] = srcA[k]; dstB[k] = srcB[k]; }
    }
    __syncthreads();

    int wx = w >> 2, wy = w & 3;
    float c[4][4][4];
    #pragma unroll
    for (int mi = 0; mi < 4; mi++)
        #pragma unroll
        for (int ni = 0; ni < 4; ni++)
            #pragma unroll
            for (int e = 0; e < 4; e++) c[mi][ni][e] = 0.f;

    int arow = wx * 64 + (lane & 15);
    int acol_off = ((lane >> 4) & 1) * 8;
    int brow_base = wy * 32 + (lane & 7);
    int bcol_off = ((lane >> 3) & 1) * 8;

    #pragma unroll
    for (int k0 = 0; k0 < 64; k0 += 16) {
        unsigned int bfr[4][2];
        #pragma unroll
        for (int ni = 0; ni < 4; ni++) {
            unsigned int baddr = (unsigned int)__cvta_generic_to_shared(
                &sB[(brow_base + ni * 8) * 72 + k0 + bcol_off]);
            asm volatile("ldmatrix.sync.aligned.m8n8.x2.shared.b16 {%0,%1}, [%2];"
                         : "=r"(bfr[ni][0]), "=r"(bfr[ni][1]) : "r"(baddr));
        }
        #pragma unroll
        for (int mi = 0; mi < 4; mi++) {
            unsigned int afr[4];
            unsigned int aaddr = (unsigned int)__cvta_generic_to_shared(
                &sA[(arow + mi * 16) * 72 + k0 + acol_off]);
            asm volatile("ldmatrix.sync.aligned.m8n8.x4.shared.b16 {%0,%1,%2,%3}, [%4];"
                         : "=r"(afr[0]), "=r"(afr[1]), "=r"(afr[2]), "=r"(afr[3]) : "r"(aaddr));
            #pragma unroll
            for (int ni = 0; ni < 4; ni++) {
                asm volatile(
                    "mma.sync.aligned.m16n8k16.row.col.f32.bf16.bf16.f32 "
                    "{%0,%1,%2,%3}, {%4,%5,%6,%7}, {%8,%9}, {%0,%1,%2,%3};"
                    : "+f"(c[mi][ni][0]), "+f"(c[mi][ni][1]), "+f"(c[mi][ni][2]), "+f"(c[mi][ni][3])
                    : "r"(afr[0]), "r"(afr[1]), "r"(afr[2]), "r"(afr[3]),
                      "r"(bfr[ni][0]), "r"(bfr[ni][1]));
            }
        }
    }
    __syncthreads();

    __nv_bfloat16* sOut = (__nv_bfloat16*)smem_raw;
    {
        int r0 = wx * 64 + (lane >> 2);
        int c0 = wy * 32 + (lane & 3) * 2;
        #pragma unroll
        for (int mi = 0; mi < 4; mi++)
            #pragma unroll
            for (int ni = 0; ni < 4; ni++) {
                int rr = r0 + mi * 16, cc = c0 + ni * 8;
                *(__nv_bfloat162*)&sOut[rr * 136 + cc] =
                    __float22bfloat162_rn(make_float2(c[mi][ni][0], c[mi][ni][1]));
                *(__nv_bfloat162*)&sOut[(rr + 8) * 136 + cc] =
                    __float22bfloat162_rn(make_float2(c[mi][ni][2], c[mi][ni][3]));
            }
    }
    __syncthreads();
    for (int idx = t; idx < 2048; idx += 256) {
        int row = idx >> 4, c16 = (idx & 15) * 8;
        uint4 v = *(uint4*)&sOut[row * 136 + c16];
        *(uint4*)&g_qkh[(size_t)h * V_SZ * V_SZ + (size_t)(X0 + row) * V_SZ + Y0 + c16] = v;
    }
}

// -------- K3: scan(bx0) + posqk(bx1) + cp(bx 2..2049) + transpose(bx 2050..18433) --------
__global__ __launch_bounds__(256) void transcp_kernel(const int* __restrict__ nw) {
    int t = threadIdx.x;
    int bx = blockIdx.x;
    if (bx >= 2050) {
        int e = bx - 2050;
        int x = e >> 3;
        int y = ((e & 7) << 8) + t;
        __nv_bfloat16 tmp[8];
        #pragma unroll
        for (int h = 0; h < 8; h++)
            tmp[h] = g_qkh[h * (V_SZ * V_SZ) + x * V_SZ + y];
        *(uint4*)&g_qkb[((size_t)(x * V_SZ + y)) * 8] = *(uint4*)tmp;
        return;
    }
    if (bx >= 2) {
        int v = bx - 2;
        __shared__ float scq[512], sck[512];
        if (t < 128) *(float4*)&scq[t * 4] = *(const float4*)&g_cq[v * 512 + t * 4];
        else         *(float4*)&sck[(t - 128) * 4] = *(const float4*)&g_ck[v * 512 + (t - 128) * 4];
        __syncthreads();
        int hj = t >> 1, half = t & 1;
        int h = hj >> 4, j = hj & 15;
        int off = j * 512 + h * 64 + half * 32;
        const float4* pk4 = (const float4*)&g_pk[off];
        const float4* pq4 = (const float4*)&g_pq[off];
        const float4* cq4 = (const float4*)&scq[h * 64 + half * 32];
        const float4* ck4 = (const float4*)&sck[h * 64 + half * 32];
        float acc = 0.f;
        #pragma unroll
        for (int k = 0; k < 8; k++) {
            float4 a = pk4[k], b = pq4[k], q = cq4[k], c = ck4[k];
            acc += q.x * a.x + q.y * a.y + q.z * a.z + q.w * a.w
                 + b.x * c.x + b.y * c.y + b.z * c.z + b.w * c.w;
        }
        acc += __shfl_xor_sync(0xffffffff, acc, 1);
        if (!half) g_cpb[(v * 16 + j) * 8 + h] = __float2bfloat16(acc);
        return;
    }
    if (bx == 1) {
        int i = t >> 4, j = t & 15;
        __nv_bfloat16 tmp[8];
        #pragma unroll
        for (int h = 0; h < 8; h++) {
            float a = 0.f;
            #pragma unroll
            for (int d = 0; d < 64; d += 4) {
                float4 q4 = *(const float4*)&g_pq[i * 512 + h * 64 + d];
                float4 k4 = *(const float4*)&g_pk[j * 512 + h * 64 + d];
                a += q4.x * k4.x + q4.y * k4.y + q4.z * k4.z + q4.w * k4.w;
            }
            tmp[h] = __float2bfloat16(a);
        }
        *(uint4*)&g_posb[t * 8] = *(uint4*)tmp;
        return;
    }
    __shared__ int s[N_NAMES];
    __shared__ int csum[32];
    for (int i = t; i < N_NAMES; i += 256) s[i] = nw[i];
    __syncthreads();
    if (t < 32) {
        int a = 0;
        for (int k = 0; k < 64; k++) a += s[t * 64 + k];
        int x = a;
        #pragma unroll
        for (int o = 1; o < 32; o <<= 1) {
            int y = __shfl_up_sync(0xffffffff, x, o);
            if (t >= o) x += y;
        }
        csum[t] = x - a;
    }
    __syncthreads();
    if (t < 32) {
        int off = csum[t];
        for (int k = 0; k < 64; k++) {
            g_segoff[t * 64 + k] = off;
            off += s[t * 64 + k];
        }
    }
}

// -------- K4: attention (stride-20 S; vectorized P loads in AV) --------
__global__ __launch_bounds__(256, 4) void attn_kernel(
    const int* __restrict__ code_g, const float* __restrict__ gamma, const float* __restrict__ beta) {
    __shared__ float sV[8 * 16 * 68];        // [h][p][68]
    __shared__ float S[8 * 16 * SROW];       // scores -> normalized probs, 16B-aligned rows
    __shared__ int code[16];

    int t = threadIdx.x;
    int b = blockIdx.x;

    if (t < 16) code[t] = code_g[b * 16 + t];
    __syncthreads();

    // V gather
    #pragma unroll
    for (int e = t; e < 2048; e += 256) {
        int p = e >> 7, r = e & 127;
        float4 cv4 = *(const float4*)&g_cv[code[p] * 512 + r * 4];
        float4 pv4 = *(const float4*)&g_pv[p * 512 + r * 4];
        float4 v;
        v.x = cv4.x + pv4.x; v.y = cv4.y + pv4.y; v.z = cv4.z + pv4.z; v.w = cv4.w + pv4.w;
        int h = r >> 4, d4 = (r & 15) * 4;
        *(float4*)&sV[(h * 16 + p) * 68 + d4] = v;
    }

    // Score gather: one (i,j) per thread, 8 heads per 16B sector
    {
        int i = t >> 4, j = t & 15;
        int cj = code[j];
        if (cj == 0) {
            #pragma unroll
            for (int h = 0; h < 8; h++) S[(h * 16 + i) * SROW + j] = -1e9f;
        } else {
            int ci = code[i];
            uint4 qk8u = *(const uint4*)&g_qkb[((size_t)((ci << 11) + cj)) * 8];
            uint4 cp8u = *(const uint4*)&g_cpb[((ci << 4) + j) * 8];
            uint4 ps8u = *(const uint4*)&g_posb[((i << 4) + j) * 8];
            const __nv_bfloat16* qk8 = (const __nv_bfloat16*)&qk8u;
            const __nv_bfloat16* cp8 = (const __nv_bfloat16*)&cp8u;
            const __nv_bfloat16* ps8 = (const __nv_bfloat16*)&ps8u;
            #pragma unroll
            for (int h = 0; h < 8; h++) {
                float s = __bfloat162float(qk8[h]) + __bfloat162float(cp8[h]) + __bfloat162float(ps8[h]);
                S[(h * 16 + i) * SROW + j] = s * TEMP_INV;
            }
        }
    }
    __syncthreads();

    // Softmax: 128 rows split across 256 threads (row, half); vectorized; pair combine via shfl.
    {
        int row = t >> 1, half = t & 1;
        float* rp = &S[row * SROW + half * 8];
        float4 a0 = *(const float4*)rp;
        float4 a1 = *(const float4*)(rp + 4);
        float m = fmaxf(fmaxf(fmaxf(a0.x, a0.y), fmaxf(a0.z, a0.w)),
                        fmaxf(fmaxf(a1.x, a1.y), fmaxf(a1.z, a1.w)));
        m = fmaxf(m, __shfl_xor_sync(0xffffffffu, m, 1));
        a0.x = __expf(a0.x - m); a0.y = __expf(a0.y - m);
        a0.z = __expf(a0.z - m); a0.w = __expf(a0.w - m);
        a1.x = __expf(a1.x - m); a1.y = __expf(a1.y - m);
        a1.z = __expf(a1.z - m); a1.w = __expf(a1.w - m);
        float sum = a0.x + a0.y + a0.z + a0.w + a1.x + a1.y + a1.z + a1.w;
        sum += __shfl_xor_sync(0xffffffffu, sum, 1);
        float inv = 1.f / sum;
        a0.x *= inv; a0.y *= inv; a0.z *= inv; a0.w *= inv;
        a1.x *= inv; a1.y *= inv; a1.z *= inv; a1.w *= inv;
        *(float4*)rp = a0;
        *(float4*)(rp + 4) = a1;
    }
    __syncthreads();

    // AV + LN + pool: warp = head. lane = (i0 = l>>3, dg = l&7).
    {
        int h = t >> 5;
        int lane = t & 31;
        int i0 = lane >> 3;
        int dg = lane & 7;

        float o[4][8];
        #pragma unroll
        for (int ii = 0; ii < 4; ii++)
            #pragma unroll
            for (int k = 0; k < 8; k++) o[ii][k] = 0.f;

        const float* Sbase = &S[(h * 16 + i0 * 4) * SROW];
        const float* Vbase = &sV[(h * 16) * 68];
        #pragma unroll
        for (int jc = 0; jc < 16; jc += 4) {
            float4 P[4];
            #pragma unroll
            for (int ii = 0; ii < 4; ii++)
                P[ii] = *(const float4*)&Sbase[ii * SROW + jc];
            #pragma unroll
            for (int jj = 0; jj < 4; jj++) {
                int j = jc + jj;
                float4 vA = *(const float4*)&Vbase[j * 68 + dg * 4];
                float4 vB = *(const float4*)&Vbase[j * 68 + 32 + dg * 4];
                #pragma unroll
                for (int ii = 0; ii < 4; ii++) {
                    float p = (jj == 0) ? P[ii].x : (jj == 1) ? P[ii].y : (jj == 2) ? P[ii].z : P[ii].w;
                    o[ii][0] = fmaf(p, vA.x, o[ii][0]);
                    o[ii][1] = fmaf(p, vA.y, o[ii][1]);
                    o[ii][2] = fmaf(p, vA.z, o[ii][2]);
                    o[ii][3] = fmaf(p, vA.w, o[ii][3]);
                    o[ii][4] = fmaf(p, vB.x, o[ii][4]);
                    o[ii][5] = fmaf(p, vB.y, o[ii][5]);
                    o[ii][6] = fmaf(p, vB.z, o[ii][6]);
                    o[ii][7] = fmaf(p, vB.w, o[ii][7]);
                }
            }
        }

        // LayerNorm per row: reduce across the 8 dg-lanes (shfl_xor 1,2,4)
        #pragma unroll
        for (int ii = 0; ii < 4; ii++) {
            float s1 = 0.f, s2 = 0.f;
            #pragma unroll
            for (int k = 0; k < 8; k++) { s1 += o[ii][k]; s2 += o[ii][k] * o[ii][k]; }
            s1 += __shfl_xor_sync(0xffffffff, s1, 1);
            s2 += __shfl_xor_sync(0xffffffff, s2, 1);
            s1 += __shfl_xor_sync(0xffffffff, s1, 2);
            s2 += __shfl_xor_sync(0xffffffff, s2, 2);
            s1 += __shfl_xor_sync(0xffffffff, s1, 4);
            s2 += __shfl_xor_sync(0xffffffff, s2, 4);
            float mu = s1 * (1.f / 64.f);
            float var = s2 * (1.f / 64.f) - mu * mu;
            float rstd = rsqrtf(var + 1e-5f);
            #pragma unroll
            for (int k = 0; k < 8; k++) o[ii][k] = (o[ii][k] - mu) * rstd;
        }

        // masked pool over rows: thread-local 4 rows, then shfl_xor 8,16 across i-groups
        float pl[8];
        #pragma unroll
        for (int k = 0; k < 8; k++) pl[k] = 0.f;
        float cntf = 0.f;
        #pragma unroll
        for (int ii = 0; ii < 4; ii++) {
            if (code[i0 * 4 + ii] != 0) {
                cntf += 1.f;
                #pragma unroll
                for (int k = 0; k < 8; k++) pl[k] += o[ii][k];
            }
        }
        #pragma unroll
        for (int k = 0; k < 8; k++) {
            pl[k] += __shfl_xor_sync(0xffffffff, pl[k], 8);
            pl[k] += __shfl_xor_sync(0xffffffff, pl[k], 16);
        }
        cntf += __shfl_xor_sync(0xffffffff, cntf, 8);
        cntf += __shfl_xor_sync(0xffffffff, cntf, 16);

        if (i0 == 0) {
            float inv = 1.f / cntf;
            float4 gA = *(const float4*)&gamma[dg * 4];
            float4 gB = *(const float4*)&gamma[32 + dg * 4];
            float4 bA = *(const float4*)&beta[dg * 4];
            float4 bB = *(const float4*)&beta[32 + dg * 4];
            float* dst = &g_pooled[b * 512 + h * 64];
            float4 wA, wB;
            wA.x = pl[0] * gA.x * inv + bA.x;
            wA.y = pl[1] * gA.y * inv + bA.y;
            wA.z = pl[2] * gA.z * inv + bA.z;
            wA.w = pl[3] * gA.w * inv + bA.w;
            wB.x = pl[4] * gB.x * inv + bB.x;
            wB.y = pl[5] * gB.y * inv + bB.y;
            wB.z = pl[6] * gB.z * inv + bB.z;
            wB.w = pl[7] * gB.w * inv + bB.w;
            *(float4*)&dst[dg * 4] = wA;
            *(float4*)&dst[32 + dg * 4] = wB;
        }
    }
}

// -------- K5: MLP --------
__global__ __launch_bounds__(128) void mlp_kernel(
    const float* __restrict__ W1, const float* __restrict__ b1,
    const float* __restrict__ W2, const float* __restrict__ b2) {
    __shared__ float sW1[128], sB1[16], sW2[128], sB2[8];
    int tid = threadIdx.x;
    if (tid < 128) { sW1[tid] = W1[tid]; sW2[tid] = W2[tid]; }
    if (tid < 16) sB1[tid] = b1[tid];
    if (tid < 8)  sB2[tid] = b2[tid];
    __syncthreads();
    int b = blockIdx.x * 2 + (tid >> 6);
    int d = tid & 63;
    float hv[8];
    #pragma unroll
    for (int h = 0; h < 8; h++) hv[h] = g_pooled[b * 512 + h * 64 + d];
    float t[16];
    #pragma unroll
    for (int u = 0; u < 16; u++) {
        float a = sB1[u];
        #pragma unroll
        for (int h = 0; h < 8; h++) a = fmaf(hv[h], sW1[h * 16 + u], a);
        t[u] = fmaxf(a, 0.f);
    }
    #pragma unroll
    for (int o = 0; o < 8; o++) {
        float a = sB2[o];
        #pragma unroll
        for (int u = 0; u < 16; u++) a = fmaf(t[u], sW2[u * 8 + o], a);
        g_xflat[b * 512 + d * 8 + o] = a;
    }
}

// -------- K6: word gather + segment mean --------
__global__ void seg_kernel(const int* __restrict__ word_code,
                           const int* __restrict__ n_words,
                           float* __restrict__ out) {
    int n = blockIdx.x;
    int tid = threadIdx.x;
    int off = g_segoff[n];
    int cnt = n_words[n];
    float inv = 1.f / (float)cnt;
    for (int c = tid; c < 512; c += 256) {
        float a = 0.f;
        for (int w = 0; w < cnt; w++) {
            int wc = word_code[off + w];
            a += g_xflat[wc * 512 + c];
        }
        out[n * 512 + c] = a * inv;
    }
}

extern "C" void kernel_launch(void* const* d_in, const int* in_sizes, int n_in,
                              void* d_out, int out_size) {
    const float* char_emb = (const float*)d_in[0];
    const float* Wc       = (const float*)d_in[1];
    const float* bc       = (const float*)d_in[2];
    const float* Wp       = (const float*)d_in[3];
    const float* bp       = (const float*)d_in[4];
    const float* gamma    = (const float*)d_in[5];
    const float* beta     = (const float*)d_in[6];
    const float* W1       = (const float*)d_in[7];
    const float* b1       = (const float*)d_in[8];
    const float* W2       = (const float*)d_in[9];
    const float* b2       = (const float*)d_in[10];
    const int* char_code  = (const int*)d_in[11];
    const int* word_code  = (const int*)d_in[12];
    const int* n_words    = (const int*)d_in[13];
    float* out = (float*)d_out;

    prep_kernel<<<272, 256>>>(Wp, bp, char_emb, Wc, bc);     // 1
    charqk_mma_kernel<<<dim3(16, 16, 8), 256>>>();           // 2
    transcp_kernel<<<18434, 256>>>(n_words);                 // 3
    attn_kernel<<<B_SZ, 256>>>(char_code, gamma, beta);      // 4 <- profiled
    mlp_kernel<<<B_SZ / 2, 128>>>(W1, b1, W2, b2);           // 5
    seg_kernel<<<N_NAMES, 256>>>(word_code, n_words, out);   // 6
}

// round 17
// speedup vs baseline: 1.0261x; 1.0261x over previous
#include <cuda_runtime.h>
#include <cuda_bf16.h>
#include <math.h>
#include <cstdint>

#define V_SZ 2048
#define L_SZ 16
#define H_SZ 8
#define D_SZ 64
#define B_SZ 8192
#define NW_TOTAL 8192
#define N_NAMES 2048
#define TEMP_INV 0.125f

// -------- scratch --------
__device__ float g_cq[V_SZ * H_SZ * D_SZ];
__device__ float g_ck[V_SZ * H_SZ * D_SZ];
__device__ float g_cv[V_SZ * H_SZ * D_SZ];
__device__ __nv_bfloat16 g_cqb[V_SZ * 512];
__device__ __nv_bfloat16 g_ckb[V_SZ * 512];
__device__ float g_pq[L_SZ * H_SZ * D_SZ];
__device__ float g_pk[L_SZ * H_SZ * D_SZ];
__device__ float g_pv[L_SZ * H_SZ * D_SZ];
__device__ __nv_bfloat16 g_qkb[V_SZ * V_SZ * H_SZ];   // 67MB [x][y][h]
__device__ __nv_bfloat16 g_cpb[V_SZ * L_SZ * H_SZ];   // [v][j][h]
__device__ __nv_bfloat16 g_posb[L_SZ * L_SZ * H_SZ];  // [i][j][h]
__device__ float g_pooled[B_SZ * H_SZ * D_SZ];
__device__ float g_xflat[B_SZ * 512];
__device__ int   g_segoff[N_NAMES];

// -------- K1: prep = pos-embed QKV (blocks 0..15) + char QKV (blocks 16..271) --------
__global__ __launch_bounds__(256) void prep_kernel(
    const float* __restrict__ Wp, const float* __restrict__ bp,
    const float* __restrict__ emb, const float* __restrict__ Wc, const float* __restrict__ bc) {
    int tid = threadIdx.x;
    if (blockIdx.x < 16) {
        int l = blockIdx.x;
        __shared__ float sp[64];
        if (tid < 64) {
            int f = tid & 31;
            double inv = pow(10000.0, -(double)f / 32.0);
            double ph = (double)l * inv;
            sp[tid] = (float)((tid < 32) ? cos(ph) : sin(ph));
        }
        __syncthreads();
        for (int c = tid; c < 1536; c += 256) {
            float a = 0.f;
            #pragma unroll 8
            for (int k = 0; k < 64; k++) a += sp[k] * Wp[k * 1536 + c];
            a += bp[c];
            int t = c >> 9, rem = c & 511;
            float* dst = (t == 0) ? g_pq : (t == 1) ? g_pk : g_pv;
            dst[l * 512 + rem] = a;
        }
        return;
    }
    int row0 = (blockIdx.x - 16) * 8;
    __shared__ float se[8][64];
    for (int idx = tid; idx < 512; idx += 256)
        se[idx >> 6][idx & 63] = emb[(row0 + (idx >> 6)) * 64 + (idx & 63)];
    __syncthreads();
    float acc[6][8];
    #pragma unroll
    for (int c = 0; c < 6; c++)
        #pragma unroll
        for (int r = 0; r < 8; r++) acc[c][r] = 0.f;
    for (int k = 0; k < 64; k++) {
        float w[6];
        #pragma unroll
        for (int c = 0; c < 6; c++) w[c] = Wc[k * 1536 + tid + c * 256];
        #pragma unroll
        for (int r = 0; r < 8; r++) {
            float e = se[r][k];
            #pragma unroll
            for (int c = 0; c < 6; c++) acc[c][r] = fmaf(e, w[c], acc[c][r]);
        }
    }
    #pragma unroll
    for (int c = 0; c < 6; c++) {
        int col = tid + c * 256;
        float bias = bc[col];
        int t = col >> 9, rem = col & 511;
        float* dst = (t == 0) ? g_cq : (t == 1) ? g_ck : g_cv;
        __nv_bfloat16* bdst = (t == 0) ? g_cqb : (t == 1) ? g_ckb : (__nv_bfloat16*)0;
        #pragma unroll
        for (int r = 0; r < 8; r++) {
            float val = acc[c][r] + bias;
            int idx = (row0 + r) * 512 + rem;
            dst[idx] = val;
            if (bdst) bdst[idx] = __float2bfloat16(val);
        }
    }
}

// -------- K2: FUSED char_qk GEMM: 64x64 (x,y)-tile x all 8 heads -> coalesced [x][y][h] --------
// dynamic smem: sA[64][72], sB[64][72], sStage[8][64][72]  = 92160 B
__global__ __launch_bounds__(256) void charqk_fused_kernel() {
    extern __shared__ __align__(16) __nv_bfloat16 smem[];
    __nv_bfloat16* sA = smem;                    // [64][72]
    __nv_bfloat16* sB = smem + 64 * 72;          // [64][72]
    __nv_bfloat16* sStage = smem + 2 * 64 * 72;  // [8][64][72]

    int t = threadIdx.x;
    int lane = t & 31;
    int w = t >> 5;
    int X0 = blockIdx.x * 64, Y0 = blockIdx.y * 64;
    int wx = w >> 1, wy = w & 1;   // warp tile: rows wx*16, cols wy*32

    int r_ld = t >> 2, q_ld = t & 3;

    int arow = wx * 16 + (lane & 15);
    int acol_off = ((lane >> 4) & 1) * 8;
    int brow_base = wy * 32 + (lane & 7);
    int bcol_off = ((lane >> 3) & 1) * 8;
    int r0 = wx * 16 + (lane >> 2);
    int c0 = wy * 32 + (lane & 3) * 2;

    #pragma unroll 1
    for (int h = 0; h < 8; h++) {
        // load A (cq) / B (ck) 64x64 bf16 tiles for this head
        {
            const uint4* srcA = (const uint4*)&g_cqb[(size_t)(X0 + r_ld) * 512 + h * 64 + q_ld * 16];
            const uint4* srcB = (const uint4*)&g_ckb[(size_t)(Y0 + r_ld) * 512 + h * 64 + q_ld * 16];
            uint4* dA = (uint4*)&sA[r_ld * 72 + q_ld * 16];
            uint4* dB = (uint4*)&sB[r_ld * 72 + q_ld * 16];
            dA[0] = srcA[0]; dA[1] = srcA[1];
            dB[0] = srcB[0]; dB[1] = srcB[1];
        }
        __syncthreads();

        float c[4][4];
        #pragma unroll
        for (int ni = 0; ni < 4; ni++)
            #pragma unroll
            for (int e = 0; e < 4; e++) c[ni][e] = 0.f;

        #pragma unroll
        for (int k0 = 0; k0 < 64; k0 += 16) {
            unsigned int afr[4];
            unsigned int aaddr = (unsigned int)__cvta_generic_to_shared(
                &sA[arow * 72 + k0 + acol_off]);
            asm volatile("ldmatrix.sync.aligned.m8n8.x4.shared.b16 {%0,%1,%2,%3}, [%4];"
                         : "=r"(afr[0]), "=r"(afr[1]), "=r"(afr[2]), "=r"(afr[3]) : "r"(aaddr));
            #pragma unroll
            for (int ni = 0; ni < 4; ni++) {
                unsigned int bfr[2];
                unsigned int baddr = (unsigned int)__cvta_generic_to_shared(
                    &sB[(brow_base + ni * 8) * 72 + k0 + bcol_off]);
                asm volatile("ldmatrix.sync.aligned.m8n8.x2.shared.b16 {%0,%1}, [%2];"
                             : "=r"(bfr[0]), "=r"(bfr[1]) : "r"(baddr));
                asm volatile(
                    "mma.sync.aligned.m16n8k16.row.col.f32.bf16.bf16.f32 "
                    "{%0,%1,%2,%3}, {%4,%5,%6,%7}, {%8,%9}, {%0,%1,%2,%3};"
                    : "+f"(c[ni][0]), "+f"(c[ni][1]), "+f"(c[ni][2]), "+f"(c[ni][3])
                    : "r"(afr[0]), "r"(afr[1]), "r"(afr[2]), "r"(afr[3]),
                      "r"(bfr[0]), "r"(bfr[1]));
            }
        }

        // stage this head's tile (conflict-free: pad-72 rotates banks by 4 per row)
        __nv_bfloat16* st = &sStage[h * 64 * 72];
        #pragma unroll
        for (int ni = 0; ni < 4; ni++) {
            int cc = c0 + ni * 8;
            *(__nv_bfloat162*)&st[r0 * 72 + cc] =
                __float22bfloat162_rn(make_float2(c[ni][0], c[ni][1]));
            *(__nv_bfloat162*)&st[(r0 + 8) * 72 + cc] =
                __float22bfloat162_rn(make_float2(c[ni][2], c[ni][3]));
        }
        __syncthreads();   // stage complete; safe to overwrite sA/sB next h
    }

    // write out: (x,y) -> 8 heads = one uint4; lanes 0..3 cover contiguous 64B
    {
        int x = t >> 2;
        #pragma unroll
        for (int rep = 0; rep < 16; rep++) {
            int y = rep * 4 + (t & 3);
            __nv_bfloat16 tmp[8];
            #pragma unroll
            for (int h = 0; h < 8; h++)
                tmp[h] = sStage[h * 64 * 72 + x * 72 + y];
            *(uint4*)&g_qkb[((size_t)((X0 + x) * V_SZ + Y0 + y)) * 8] = *(uint4*)tmp;
        }
    }
}

// -------- K3: scan(bx0) + posqk(bx1) + cp(bx 2..2049) --------
__global__ __launch_bounds__(256) void transcp_kernel(const int* __restrict__ nw) {
    int t = threadIdx.x;
    int bx = blockIdx.x;
    if (bx >= 2) {
        int v = bx - 2;
        __shared__ float scq[512], sck[512];
        if (t < 128) *(float4*)&scq[t * 4] = *(const float4*)&g_cq[v * 512 + t * 4];
        else         *(float4*)&sck[(t - 128) * 4] = *(const float4*)&g_ck[v * 512 + (t - 128) * 4];
        __syncthreads();
        int hj = t >> 1, half = t & 1;
        int h = hj >> 4, j = hj & 15;
        int off = j * 512 + h * 64 + half * 32;
        const float4* pk4 = (const float4*)&g_pk[off];
        const float4* pq4 = (const float4*)&g_pq[off];
        const float4* cq4 = (const float4*)&scq[h * 64 + half * 32];
        const float4* ck4 = (const float4*)&sck[h * 64 + half * 32];
        float acc = 0.f;
        #pragma unroll
        for (int k = 0; k < 8; k++) {
            float4 a = pk4[k], b = pq4[k], q = cq4[k], c = ck4[k];
            acc += q.x * a.x + q.y * a.y + q.z * a.z + q.w * a.w
                 + b.x * c.x + b.y * c.y + b.z * c.z + b.w * c.w;
        }
        acc += __shfl_xor_sync(0xffffffff, acc, 1);
        if (!half) g_cpb[(v * 16 + j) * 8 + h] = __float2bfloat16(acc);
        return;
    }
    if (bx == 1) {
        int i = t >> 4, j = t & 15;
        __nv_bfloat16 tmp[8];
        #pragma unroll
        for (int h = 0; h < 8; h++) {
            float a = 0.f;
            #pragma unroll
            for (int d = 0; d < 64; d += 4) {
                float4 q4 = *(const float4*)&g_pq[i * 512 + h * 64 + d];
                float4 k4 = *(const float4*)&g_pk[j * 512 + h * 64 + d];
                a += q4.x * k4.x + q4.y * k4.y + q4.z * k4.z + q4.w * k4.w;
            }
            tmp[h] = __float2bfloat16(a);
        }
        *(uint4*)&g_posb[t * 8] = *(uint4*)tmp;
        return;
    }
    __shared__ int s[N_NAMES];
    __shared__ int csum[32];
    for (int i = t; i < N_NAMES; i += 256) s[i] = nw[i];
    __syncthreads();
    if (t < 32) {
        int a = 0;
        for (int k = 0; k < 64; k++) a += s[t * 64 + k];
        int x = a;
        #pragma unroll
        for (int o = 1; o < 32; o <<= 1) {
            int y = __shfl_up_sync(0xffffffff, x, o);
            if (t >= o) x += y;
        }
        csum[t] = x - a;
    }
    __syncthreads();
    if (t < 32) {
        int off = csum[t];
        for (int k = 0; k < 64; k++) {
            g_segoff[t * 64 + k] = off;
            off += s[t * 64 + k];
        }
    }
}

// -------- K4: attention (R11-exact) --------
__global__ __launch_bounds__(256, 4) void attn_kernel(
    const int* __restrict__ code_g, const float* __restrict__ gamma, const float* __restrict__ beta) {
    __shared__ float sV[8 * 16 * 68];     // [h][p][68]
    __shared__ float S[8 * 16 * 17];      // normalized probs after softmax
    __shared__ int code[16];

    int t = threadIdx.x;
    int b = blockIdx.x;

    if (t < 16) code[t] = code_g[b * 16 + t];
    __syncthreads();

    // V gather
    #pragma unroll
    for (int e = t; e < 2048; e += 256) {
        int p = e >> 7, r = e & 127;
        float4 cv4 = *(const float4*)&g_cv[code[p] * 512 + r * 4];
        float4 pv4 = *(const float4*)&g_pv[p * 512 + r * 4];
        float4 v;
        v.x = cv4.x + pv4.x; v.y = cv4.y + pv4.y; v.z = cv4.z + pv4.z; v.w = cv4.w + pv4.w;
        int h = r >> 4, d4 = (r & 15) * 4;
        *(float4*)&sV[(h * 16 + p) * 68 + d4] = v;
    }

    // Score gather: one (i,j) per thread, 8 heads per 16B sector
    {
        int i = t >> 4, j = t & 15;
        int cj = code[j];
        if (cj == 0) {
            #pragma unroll
            for (int h = 0; h < 8; h++) S[(h * 16 + i) * 17 + j] = -1e9f;
        } else {
            int ci = code[i];
            uint4 qk8u = *(const uint4*)&g_qkb[((size_t)((ci << 11) + cj)) * 8];
            uint4 cp8u = *(const uint4*)&g_cpb[((ci << 4) + j) * 8];
            uint4 ps8u = *(const uint4*)&g_posb[((i << 4) + j) * 8];
            const __nv_bfloat16* qk8 = (const __nv_bfloat16*)&qk8u;
            const __nv_bfloat16* cp8 = (const __nv_bfloat16*)&cp8u;
            const __nv_bfloat16* ps8 = (const __nv_bfloat16*)&ps8u;
            #pragma unroll
            for (int h = 0; h < 8; h++) {
                float s = __bfloat162float(qk8[h]) + __bfloat162float(cp8[h]) + __bfloat162float(ps8[h]);
                S[(h * 16 + i) * 17 + j] = s * TEMP_INV;
            }
        }
    }
    __syncthreads();

    // Softmax: 128 rows; store NORMALIZED probabilities
    if (t < 128) {
        float* row = &S[t * 17];
        float m = -1e30f;
        #pragma unroll
        for (int j = 0; j < 16; j++) m = fmaxf(m, row[j]);
        float sum = 0.f;
        float e[16];
        #pragma unroll
        for (int j = 0; j < 16; j++) {
            e[j] = expf(row[j] - m);
            sum += e[j];
        }
        float inv = 1.f / sum;
        #pragma unroll
        for (int j = 0; j < 16; j++) row[j] = e[j] * inv;
    }
    __syncthreads();

    // AV + LN + pool: warp = head. lane = (i0 = l>>3, dg = l&7).
    {
        int h = t >> 5;
        int lane = t & 31;
        int i0 = lane >> 3;
        int dg = lane & 7;

        float o[4][8];
        #pragma unroll
        for (int ii = 0; ii < 4; ii++)
            #pragma unroll
            for (int k = 0; k < 8; k++) o[ii][k] = 0.f;

        const float* Sbase = &S[(h * 16 + i0 * 4) * 17];
        const float* Vbase = &sV[(h * 16) * 68];
        #pragma unroll
        for (int j = 0; j < 16; j++) {
            float4 vA = *(const float4*)&Vbase[j * 68 + dg * 4];
            float4 vB = *(const float4*)&Vbase[j * 68 + 32 + dg * 4];
            #pragma unroll
            for (int ii = 0; ii < 4; ii++) {
                float p = Sbase[ii * 17 + j];
                o[ii][0] = fmaf(p, vA.x, o[ii][0]);
                o[ii][1] = fmaf(p, vA.y, o[ii][1]);
                o[ii][2] = fmaf(p, vA.z, o[ii][2]);
                o[ii][3] = fmaf(p, vA.w, o[ii][3]);
                o[ii][4] = fmaf(p, vB.x, o[ii][4]);
                o[ii][5] = fmaf(p, vB.y, o[ii][5]);
                o[ii][6] = fmaf(p, vB.z, o[ii][6]);
                o[ii][7] = fmaf(p, vB.w, o[ii][7]);
            }
        }

        // LayerNorm per row: reduce across the 8 dg-lanes (shfl_xor 1,2,4)
        #pragma unroll
        for (int ii = 0; ii < 4; ii++) {
            float s1 = 0.f, s2 = 0.f;
            #pragma unroll
            for (int k = 0; k < 8; k++) { s1 += o[ii][k]; s2 += o[ii][k] * o[ii][k]; }
            s1 += __shfl_xor_sync(0xffffffff, s1, 1);
            s2 += __shfl_xor_sync(0xffffffff, s2, 1);
            s1 += __shfl_xor_sync(0xffffffff, s1, 2);
            s2 += __shfl_xor_sync(0xffffffff, s2, 2);
            s1 += __shfl_xor_sync(0xffffffff, s1, 4);
            s2 += __shfl_xor_sync(0xffffffff, s2, 4);
            float mu = s1 * (1.f / 64.f);
            float var = s2 * (1.f / 64.f) - mu * mu;
            float rstd = rsqrtf(var + 1e-5f);
            #pragma unroll
            for (int k = 0; k < 8; k++) o[ii][k] = (o[ii][k] - mu) * rstd;
        }

        // masked pool over rows: thread-local 4 rows, then shfl_xor 8,16 across i-groups
        float pl[8];
        #pragma unroll
        for (int k = 0; k < 8; k++) pl[k] = 0.f;
        float cntf = 0.f;
        #pragma unroll
        for (int ii = 0; ii < 4; ii++) {
            if (code[i0 * 4 + ii] != 0) {
                cntf += 1.f;
                #pragma unroll
                for (int k = 0; k < 8; k++) pl[k] += o[ii][k];
            }
        }
        #pragma unroll
        for (int k = 0; k < 8; k++) {
            pl[k] += __shfl_xor_sync(0xffffffff, pl[k], 8);
            pl[k] += __shfl_xor_sync(0xffffffff, pl[k], 16);
        }
        cntf += __shfl_xor_sync(0xffffffff, cntf, 8);
        cntf += __shfl_xor_sync(0xffffffff, cntf, 16);

        if (i0 == 0) {
            float inv = 1.f / cntf;
            float4 gA = *(const float4*)&gamma[dg * 4];
            float4 gB = *(const float4*)&gamma[32 + dg * 4];
            float4 bA = *(const float4*)&beta[dg * 4];
            float4 bB = *(const float4*)&beta[32 + dg * 4];
            float* dst = &g_pooled[b * 512 + h * 64];
            float4 wA, wB;
            wA.x = pl[0] * gA.x * inv + bA.x;
            wA.y = pl[1] * gA.y * inv + bA.y;
            wA.z = pl[2] * gA.z * inv + bA.z;
            wA.w = pl[3] * gA.w * inv + bA.w;
            wB.x = pl[4] * gB.x * inv + bB.x;
            wB.y = pl[5] * gB.y * inv + bB.y;
            wB.z = pl[6] * gB.z * inv + bB.z;
            wB.w = pl[7] * gB.w * inv + bB.w;
            *(float4*)&dst[dg * 4] = wA;
            *(float4*)&dst[32 + dg * 4] = wB;
        }
    }
}

// -------- K5: MLP --------
__global__ __launch_bounds__(128) void mlp_kernel(
    const float* __restrict__ W1, const float* __restrict__ b1,
    const float* __restrict__ W2, const float* __restrict__ b2) {
    __shared__ float sW1[128], sB1[16], sW2[128], sB2[8];
    int tid = threadIdx.x;
    if (tid < 128) { sW1[tid] = W1[tid]; sW2[tid] = W2[tid]; }
    if (tid < 16) sB1[tid] = b1[tid];
    if (tid < 8)  sB2[tid] = b2[tid];
    __syncthreads();
    int b = blockIdx.x * 2 + (tid >> 6);
    int d = tid & 63;
    float hv[8];
    #pragma unroll
    for (int h = 0; h < 8; h++) hv[h] = g_pooled[b * 512 + h * 64 + d];
    float t[16];
    #pragma unroll
    for (int u = 0; u < 16; u++) {
        float a = sB1[u];
        #pragma unroll
        for (int h = 0; h < 8; h++) a = fmaf(hv[h], sW1[h * 16 + u], a);
        t[u] = fmaxf(a, 0.f);
    }
    #pragma unroll
    for (int o = 0; o < 8; o++) {
        float a = sB2[o];
        #pragma unroll
        for (int u = 0; u < 16; u++) a = fmaf(t[u], sW2[u * 8 + o], a);
        g_xflat[b * 512 + d * 8 + o] = a;
    }
}

// -------- K6: word gather + segment mean --------
__global__ void seg_kernel(const int* __restrict__ word_code,
                           const int* __restrict__ n_words,
                           float* __restrict__ out) {
    int n = blockIdx.x;
    int tid = threadIdx.x;
    int off = g_segoff[n];
    int cnt = n_words[n];
    float inv = 1.f / (float)cnt;
    for (int c = tid; c < 512; c += 256) {
        float a = 0.f;
        for (int w = 0; w < cnt; w++) {
            int wc = word_code[off + w];
            a += g_xflat[wc * 512 + c];
        }
        out[n * 512 + c] = a * inv;
    }
}

extern "C" void kernel_launch(void* const* d_in, const int* in_sizes, int n_in,
                              void* d_out, int out_size) {
    const float* char_emb = (const float*)d_in[0];
    const float* Wc       = (const float*)d_in[1];
    const float* bc       = (const float*)d_in[2];
    const float* Wp       = (const float*)d_in[3];
    const float* bp       = (const float*)d_in[4];
    const float* gamma    = (const float*)d_in[5];
    const float* beta     = (const float*)d_in[6];
    const float* W1       = (const float*)d_in[7];
    const float* b1       = (const float*)d_in[8];
    const float* W2       = (const float*)d_in[9];
    const float* b2       = (const float*)d_in[10];
    const int* char_code  = (const int*)d_in[11];
    const int* word_code  = (const int*)d_in[12];
    const int* n_words    = (const int*)d_in[13];
    float* out = (float*)d_out;

    static bool attr_set = false;
    if (!attr_set) {
        cudaFuncSetAttribute(charqk_fused_kernel,
                             cudaFuncAttributeMaxDynamicSharedMemorySize, 92160);
        attr_set = true;
    }

    prep_kernel<<<272, 256>>>(Wp, bp, char_emb, Wc, bc);        // 1
    charqk_fused_kernel<<<dim3(32, 32), 256, 92160>>>();        // 2
    transcp_kernel<<<2050, 256>>>(n_words);                     // 3
    attn_kernel<<<B_SZ, 256>>>(char_code, gamma, beta);         // 4 <- profiled
    mlp_kernel<<<B_SZ / 2, 128>>>(W1, b1, W2, b2);              // 5
    seg_kernel<<<N_NAMES, 256>>>(word_code, n_words, out);      // 6
}